// round 12
// baseline (speedup 1.0000x reference)
#include <cuda_runtime.h>

#define BB 8
#define SS 2048
#define DD 1024
#define LRATE 0.01f

typedef unsigned long long u64;

// Scratch for projected views K, V, Q: [B*S, D] each (64MB each).
__device__ float g_K[BB * SS * DD];
__device__ float g_V[BB * SS * DD];
__device__ float g_Q[BB * SS * DD];

// ---------------- packed f32x2 helpers (FFMA2: 2 MACs/instr) ----------------
__device__ __forceinline__ u64 pk2(float x, float y) {
    u64 r; asm("mov.b64 %0, {%1, %2};" : "=l"(r) : "f"(x), "f"(y)); return r;
}
__device__ __forceinline__ float2 upk2(u64 v) {
    float2 r; asm("mov.b64 {%0, %1}, %2;" : "=f"(r.x), "=f"(r.y) : "l"(v)); return r;
}
__device__ __forceinline__ u64 f2fma(u64 a, u64 b, u64 c) {
    u64 d; asm("fma.rn.f32x2 %0, %1, %2, %3;" : "=l"(d) : "l"(a), "l"(b), "l"(c)); return d;
}
__device__ __forceinline__ float warpsum(float v) {
#pragma unroll
    for (int o = 16; o > 0; o >>= 1) v += __shfl_xor_sync(0xffffffffu, v, o);
    return v;
}
__device__ __forceinline__ float redu(u64 v) {   // pair-sum + warp reduce
    const float2 p = upk2(v);
    return warpsum(p.x + p.y);
}

// ======================= Projection GEMM =======================
// C[m][n] = sum_k A[m][k] * Th[n][k]   (both K-major "NT" GEMM)
// M = B*S = 16384, N = 1024, K = 1024.  blockIdx.z selects view.
#define GBM 128
#define GBN 128
#define GBK 16
#define GPAD 132
#define KITERS (DD / GBK)     // 64

__global__ void __launch_bounds__(256, 1) proj_kernel(
    const float* __restrict__ A,
    const float* __restrict__ T0,
    const float* __restrict__ T1,
    const float* __restrict__ T2)
{
    __shared__ __align__(16) float As[GBK][GPAD];
    __shared__ __align__(16) float Bs[GBK][GPAD];

    const float* Th = (blockIdx.z == 0) ? T0 : ((blockIdx.z == 1) ? T1 : T2);
    float* C = (blockIdx.z == 0) ? g_K : ((blockIdx.z == 1) ? g_V : g_Q);

    const int m0 = blockIdx.x * GBM;
    const int n0 = blockIdx.y * GBN;
    const int tid = threadIdx.x;
    const int tx = tid & 15, ty = tid >> 4;

    u64 acc[8][4];
#pragma unroll
    for (int i = 0; i < 8; i++)
#pragma unroll
        for (int p = 0; p < 4; p++) acc[i][p] = 0ull;

    const int r0 = tid >> 2;
    const int kq = tid & 3;

    float4 ra0 = *(const float4*)&A [(m0 + r0)      * DD + 4 * kq];
    float4 ra1 = *(const float4*)&A [(m0 + r0 + 64) * DD + 4 * kq];
    float4 rb0 = *(const float4*)&Th[(n0 + r0)      * DD + 4 * kq];
    float4 rb1 = *(const float4*)&Th[(n0 + r0 + 64) * DD + 4 * kq];

    for (int kt = 0; kt < KITERS; kt++) {
        As[4 * kq + 0][r0] = ra0.x; As[4 * kq + 1][r0] = ra0.y;
        As[4 * kq + 2][r0] = ra0.z; As[4 * kq + 3][r0] = ra0.w;
        As[4 * kq + 0][r0 + 64] = ra1.x; As[4 * kq + 1][r0 + 64] = ra1.y;
        As[4 * kq + 2][r0 + 64] = ra1.z; As[4 * kq + 3][r0 + 64] = ra1.w;
        Bs[4 * kq + 0][r0] = rb0.x; Bs[4 * kq + 1][r0] = rb0.y;
        Bs[4 * kq + 2][r0] = rb0.z; Bs[4 * kq + 3][r0] = rb0.w;
        Bs[4 * kq + 0][r0 + 64] = rb1.x; Bs[4 * kq + 1][r0 + 64] = rb1.y;
        Bs[4 * kq + 2][r0 + 64] = rb1.z; Bs[4 * kq + 3][r0 + 64] = rb1.w;
        __syncthreads();

        if (kt + 1 < KITERS) {
            const int kb = (kt + 1) * GBK + 4 * kq;
            ra0 = *(const float4*)&A [(m0 + r0)      * DD + kb];
            ra1 = *(const float4*)&A [(m0 + r0 + 64) * DD + kb];
            rb0 = *(const float4*)&Th[(n0 + r0)      * DD + kb];
            rb1 = *(const float4*)&Th[(n0 + r0 + 64) * DD + kb];
        }

#pragma unroll
        for (int kk = 0; kk < GBK; kk++) {
            const float4 a0 = *(const float4*)&As[kk][ty * 8];
            const float4 a1 = *(const float4*)&As[kk][ty * 8 + 4];
            const ulonglong2 b01 = *(const ulonglong2*)&Bs[kk][tx * 8];
            const ulonglong2 b23 = *(const ulonglong2*)&Bs[kk][tx * 8 + 4];
            u64 bp[4] = {b01.x, b01.y, b23.x, b23.y};
            const float av[8] = {a0.x, a0.y, a0.z, a0.w, a1.x, a1.y, a1.z, a1.w};
#pragma unroll
            for (int i = 0; i < 8; i++) {
                const u64 ap = pk2(av[i], av[i]);
#pragma unroll
                for (int p = 0; p < 4; p++) acc[i][p] = f2fma(ap, bp[p], acc[i][p]);
            }
        }
        __syncthreads();
    }

#pragma unroll
    for (int i = 0; i < 8; i++) {
        const int m = m0 + ty * 8 + i;
        const float2 q0 = upk2(acc[i][0]), q1 = upk2(acc[i][1]);
        const float2 q2 = upk2(acc[i][2]), q3 = upk2(acc[i][3]);
        *(float4*)&C[m * DD + n0 + tx * 8]     = make_float4(q0.x, q0.y, q1.x, q1.y);
        *(float4*)&C[m * DD + n0 + tx * 8 + 4] = make_float4(q2.x, q2.y, q3.x, q3.y);
    }
}

// ======================= Persistent TTT scan (rank-4 token blocking) =======
// 128 blocks (16 row-chunks x 8 batches), single wave, 512 threads.
// Warp w owns rows base+4w..base+4w+3: rows 0..2 in SMEM (48 rows = 192KB),
// row 3 in registers (wr[8], 32 regs).
// Per group of 4 tokens (exact dual form):
//   mg_t[r] = -LR*g_t[r] = cm*(W0 k_t + b0 + sum_{i<t} mg_i (k_i.k_t+1) - v_t)
//   W4 = W0 + sum_t mg_t k_t^T
//   out_t = W4 q_t + b4 - sum_{i>t} mg_i (k_i.q_t + 1)
#define SMEM_ROWS 48
#define SCAN_SMEM (SMEM_ROWS * DD * 4)
#define TSTRIDE (DD / 4)      // ulonglong2 (16B) per token row = 256  [R10 FIX]

__global__ void __launch_bounds__(512, 1) scan_kernel(
    const float* __restrict__ W0,
    const float* __restrict__ b0,
    float* __restrict__ out)
{
    extern __shared__ __align__(16) float Wsh[];
    ulonglong2* Wsh2 = (ulonglong2*)Wsh;

    const int tid = threadIdx.x;
    const int w = tid >> 5;
    const int lane = tid & 31;
    const int batch = blockIdx.y;
    const int row0 = blockIdx.x * 64;
    const int rbase = row0 + 4 * w;       // first of this warp's 4 rows

    // ---- init W slice ----
    {
        const float4* W04 = (const float4*)W0;
        float4* Wsh4 = (float4*)Wsh;
        for (int i = tid; i < SMEM_ROWS * 256; i += 512) {
            const int s = i >> 8;
            const int c = i & 255;
            const int grow = row0 + (s / 3) * 4 + (s % 3);
            Wsh4[i] = W04[grow * 256 + c];
        }
    }
    ulonglong2 wr[8];                     // register row = rbase + 3
    {
        const ulonglong2* W02 = (const ulonglong2*)W0;
        const int gr3 = rbase + 3;
#pragma unroll
        for (int j = 0; j < 8; j++) wr[j] = W02[gr3 * 256 + lane + 32 * j];
    }
    float bv[4];
#pragma unroll
    for (int i = 0; i < 4; i++) bv[i] = b0[rbase + i];
    __syncthreads();

    const ulonglong2* kB = (const ulonglong2*)(g_K + batch * SS * DD);
    const ulonglong2* qB = (const ulonglong2*)(g_Q + batch * SS * DD);
    const float* Vb = g_V + batch * SS * DD;
    float* Ob = out + (size_t)batch * SS * DD;

    const float cm = -LRATE * 2.0f / (float)DD;
    const int s0 = (3 * w + 0) * 256 + lane;
    const int s1 = (3 * w + 1) * 256 + lane;
    const int s2 = (3 * w + 2) * 256 + lane;

    for (int gt = 0; gt < SS / 4; gt++) {
        // ================= phase 0: cross dots KK (i<t), KQ (i>t) ==========
        u64 kka[6], kqa[6];
#pragma unroll
        for (int p = 0; p < 6; p++) { kka[p] = 0ull; kqa[p] = 0ull; }
#pragma unroll
        for (int j = 0; j < 8; j++) {
            const int idx = lane + 32 * j;
            const ulonglong2 k0v = __ldg(kB + idx);
            const ulonglong2 k1v = __ldg(kB + idx + TSTRIDE);
            const ulonglong2 k2v = __ldg(kB + idx + 2 * TSTRIDE);
            const ulonglong2 k3v = __ldg(kB + idx + 3 * TSTRIDE);
            const ulonglong2 q0v = __ldg(qB + idx);
            const ulonglong2 q1v = __ldg(qB + idx + TSTRIDE);
            const ulonglong2 q2v = __ldg(qB + idx + 2 * TSTRIDE);
            // KK pairs (i<t): 01 02 03 12 13 23
            kka[0] = f2fma(k0v.x, k1v.x, kka[0]); kka[0] = f2fma(k0v.y, k1v.y, kka[0]);
            kka[1] = f2fma(k0v.x, k2v.x, kka[1]); kka[1] = f2fma(k0v.y, k2v.y, kka[1]);
            kka[2] = f2fma(k0v.x, k3v.x, kka[2]); kka[2] = f2fma(k0v.y, k3v.y, kka[2]);
            kka[3] = f2fma(k1v.x, k2v.x, kka[3]); kka[3] = f2fma(k1v.y, k2v.y, kka[3]);
            kka[4] = f2fma(k1v.x, k3v.x, kka[4]); kka[4] = f2fma(k1v.y, k3v.y, kka[4]);
            kka[5] = f2fma(k2v.x, k3v.x, kka[5]); kka[5] = f2fma(k2v.y, k3v.y, kka[5]);
            // KQ pairs (i>t): k1.q0 k2.q0 k3.q0 k2.q1 k3.q1 k3.q2
            kqa[0] = f2fma(k1v.x, q0v.x, kqa[0]); kqa[0] = f2fma(k1v.y, q0v.y, kqa[0]);
            kqa[1] = f2fma(k2v.x, q0v.x, kqa[1]); kqa[1] = f2fma(k2v.y, q0v.y, kqa[1]);
            kqa[2] = f2fma(k3v.x, q0v.x, kqa[2]); kqa[2] = f2fma(k3v.y, q0v.y, kqa[2]);
            kqa[3] = f2fma(k2v.x, q1v.x, kqa[3]); kqa[3] = f2fma(k2v.y, q1v.y, kqa[3]);
            kqa[4] = f2fma(k3v.x, q1v.x, kqa[4]); kqa[4] = f2fma(k3v.y, q1v.y, kqa[4]);
            kqa[5] = f2fma(k3v.x, q2v.x, kqa[5]); kqa[5] = f2fma(k3v.y, q2v.y, kqa[5]);
        }
        float KKp[6], KQp[6];
#pragma unroll
        for (int p = 0; p < 6; p++) KKp[p] = redu(kka[p]) + 1.0f;
#pragma unroll
        for (int p = 0; p < 6; p++) KQp[p] = redu(kqa[p]) + 1.0f;

        // ================= phase A: dk[t][r] = W0 rows . k_t ===============
        u64 dka[16];
#pragma unroll
        for (int i = 0; i < 16; i++) dka[i] = 0ull;
#pragma unroll
        for (int j = 0; j < 8; j++) {
            const int idx = lane + 32 * j;
            const ulonglong2 w0v = Wsh2[s0 + 32 * j];
            const ulonglong2 w1v = Wsh2[s1 + 32 * j];
            const ulonglong2 w2v = Wsh2[s2 + 32 * j];
            const ulonglong2 wrv = wr[j];
#pragma unroll
            for (int t = 0; t < 4; t++) {
                const ulonglong2 kv = __ldg(kB + idx + t * TSTRIDE);
                dka[t * 4 + 0] = f2fma(w0v.x, kv.x, dka[t * 4 + 0]);
                dka[t * 4 + 0] = f2fma(w0v.y, kv.y, dka[t * 4 + 0]);
                dka[t * 4 + 1] = f2fma(w1v.x, kv.x, dka[t * 4 + 1]);
                dka[t * 4 + 1] = f2fma(w1v.y, kv.y, dka[t * 4 + 1]);
                dka[t * 4 + 2] = f2fma(w2v.x, kv.x, dka[t * 4 + 2]);
                dka[t * 4 + 2] = f2fma(w2v.y, kv.y, dka[t * 4 + 2]);
                dka[t * 4 + 3] = f2fma(wrv.x, kv.x, dka[t * 4 + 3]);
                dka[t * 4 + 3] = f2fma(wrv.y, kv.y, dka[t * 4 + 3]);
            }
        }
        float dkb[16];
#pragma unroll
        for (int i = 0; i < 16; i++) dkb[i] = redu(dka[i]);

        // ================= sequential recurrence (scalars) =================
        const float4 v0 = __ldg((const float4*)(Vb + (0) * DD + rbase));
        const float4 v1 = __ldg((const float4*)(Vb + (1) * DD + rbase));
        const float4 v2 = __ldg((const float4*)(Vb + (2) * DD + rbase));
        const float4 v3 = __ldg((const float4*)(Vb + (3) * DD + rbase));
        const float vv[16] = {v0.x, v0.y, v0.z, v0.w, v1.x, v1.y, v1.z, v1.w,
                              v2.x, v2.y, v2.z, v2.w, v3.x, v3.y, v3.z, v3.w};
        float mg[16];
#pragma unroll
        for (int r = 0; r < 4; r++) {
            const float m0v = cm * (dkb[0 + r] + bv[r] - vv[0 + r]);
            const float m1v = cm * (dkb[4 + r] + bv[r] + m0v * KKp[0] - vv[4 + r]);
            const float m2v = cm * (dkb[8 + r] + bv[r] + m0v * KKp[1] + m1v * KKp[3] - vv[8 + r]);
            const float m3v = cm * (dkb[12 + r] + bv[r] + m0v * KKp[2] + m1v * KKp[4] + m2v * KKp[5] - vv[12 + r]);
            mg[0 + r] = m0v; mg[4 + r] = m1v; mg[8 + r] = m2v; mg[12 + r] = m3v;
            bv[r] += m0v + m1v + m2v + m3v;    // b4
        }
        u64 mgp[16];
#pragma unroll
        for (int i = 0; i < 16; i++) mgp[i] = pk2(mg[i], mg[i]);

        // ============ phase B1: W += sum_t mg_t k_t^T ; dots q0,q1 =========
        u64 dqa01[8];
#pragma unroll
        for (int i = 0; i < 8; i++) dqa01[i] = 0ull;
#pragma unroll
        for (int j = 0; j < 8; j++) {
            const int idx = lane + 32 * j;
            ulonglong2 w0v = Wsh2[s0 + 32 * j];
            ulonglong2 w1v = Wsh2[s1 + 32 * j];
            ulonglong2 w2v = Wsh2[s2 + 32 * j];
#pragma unroll
            for (int t = 0; t < 4; t++) {
                const ulonglong2 kv = __ldg(kB + idx + t * TSTRIDE);
                w0v.x = f2fma(mgp[t * 4 + 0], kv.x, w0v.x);
                w0v.y = f2fma(mgp[t * 4 + 0], kv.y, w0v.y);
                w1v.x = f2fma(mgp[t * 4 + 1], kv.x, w1v.x);
                w1v.y = f2fma(mgp[t * 4 + 1], kv.y, w1v.y);
                w2v.x = f2fma(mgp[t * 4 + 2], kv.x, w2v.x);
                w2v.y = f2fma(mgp[t * 4 + 2], kv.y, w2v.y);
                wr[j].x = f2fma(mgp[t * 4 + 3], kv.x, wr[j].x);
                wr[j].y = f2fma(mgp[t * 4 + 3], kv.y, wr[j].y);
            }
            Wsh2[s0 + 32 * j] = w0v;
            Wsh2[s1 + 32 * j] = w1v;
            Wsh2[s2 + 32 * j] = w2v;
#pragma unroll
            for (int t = 0; t < 2; t++) {
                const ulonglong2 qv = __ldg(qB + idx + t * TSTRIDE);
                dqa01[t * 4 + 0] = f2fma(w0v.x, qv.x, dqa01[t * 4 + 0]);
                dqa01[t * 4 + 0] = f2fma(w0v.y, qv.y, dqa01[t * 4 + 0]);
                dqa01[t * 4 + 1] = f2fma(w1v.x, qv.x, dqa01[t * 4 + 1]);
                dqa01[t * 4 + 1] = f2fma(w1v.y, qv.y, dqa01[t * 4 + 1]);
                dqa01[t * 4 + 2] = f2fma(w2v.x, qv.x, dqa01[t * 4 + 2]);
                dqa01[t * 4 + 2] = f2fma(w2v.y, qv.y, dqa01[t * 4 + 2]);
                dqa01[t * 4 + 3] = f2fma(wr[j].x, qv.x, dqa01[t * 4 + 3]);
                dqa01[t * 4 + 3] = f2fma(wr[j].y, qv.y, dqa01[t * 4 + 3]);
            }
        }
        float dqs01[8];
#pragma unroll
        for (int i = 0; i < 8; i++) dqs01[i] = redu(dqa01[i]);

        // ============ phase B2: dots q2,q3 against updated W ===============
        u64 dqa23[8];
#pragma unroll
        for (int i = 0; i < 8; i++) dqa23[i] = 0ull;
#pragma unroll
        for (int j = 0; j < 8; j++) {
            const int idx = lane + 32 * j;
            const ulonglong2 w0v = Wsh2[s0 + 32 * j];
            const ulonglong2 w1v = Wsh2[s1 + 32 * j];
            const ulonglong2 w2v = Wsh2[s2 + 32 * j];
            const ulonglong2 wrv = wr[j];
#pragma unroll
            for (int t = 0; t < 2; t++) {
                const ulonglong2 qv = __ldg(qB + idx + (t + 2) * TSTRIDE);
                dqa23[t * 4 + 0] = f2fma(w0v.x, qv.x, dqa23[t * 4 + 0]);
                dqa23[t * 4 + 0] = f2fma(w0v.y, qv.y, dqa23[t * 4 + 0]);
                dqa23[t * 4 + 1] = f2fma(w1v.x, qv.x, dqa23[t * 4 + 1]);
                dqa23[t * 4 + 1] = f2fma(w1v.y, qv.y, dqa23[t * 4 + 1]);
                dqa23[t * 4 + 2] = f2fma(w2v.x, qv.x, dqa23[t * 4 + 2]);
                dqa23[t * 4 + 2] = f2fma(w2v.y, qv.y, dqa23[t * 4 + 2]);
                dqa23[t * 4 + 3] = f2fma(wrv.x, qv.x, dqa23[t * 4 + 3]);
                dqa23[t * 4 + 3] = f2fma(wrv.y, qv.y, dqa23[t * 4 + 3]);
            }
        }
        float dqs23[8];
#pragma unroll
        for (int i = 0; i < 8; i++) dqs23[i] = redu(dqa23[i]);

        // ================= epilogue: outputs with dual-form correction =====
        // out_t[r] = (W4 q_t)[r] + b4[r] - sum_{i>t} mg_i[r] * (k_i.q_t + 1)
        if (lane == 0) {
            float o[16];
#pragma unroll
            for (int r = 0; r < 4; r++) {
                o[0 + r]  = dqs01[0 + r] + bv[r]
                          - (mg[4 + r] * KQp[0] + mg[8 + r] * KQp[1] + mg[12 + r] * KQp[2]);
                o[4 + r]  = dqs01[4 + r] + bv[r]
                          - (mg[8 + r] * KQp[3] + mg[12 + r] * KQp[4]);
                o[8 + r]  = dqs23[0 + r] + bv[r] - (mg[12 + r] * KQp[5]);
                o[12 + r] = dqs23[4 + r] + bv[r];
            }
            *(float4*)(Ob + 0 * DD + rbase) = make_float4(o[0], o[1], o[2], o[3]);
            *(float4*)(Ob + 1 * DD + rbase) = make_float4(o[4], o[5], o[6], o[7]);
            *(float4*)(Ob + 2 * DD + rbase) = make_float4(o[8], o[9], o[10], o[11]);
            *(float4*)(Ob + 3 * DD + rbase) = make_float4(o[12], o[13], o[14], o[15]);
        }

        // advance to next 4-token group
        kB += 4 * TSTRIDE;
        qB += 4 * TSTRIDE;
        Vb += 4 * DD;
        Ob += 4 * DD;
    }
}

// ======================= launch =======================
extern "C" void kernel_launch(void* const* d_in, const int* in_sizes, int n_in,
                              void* d_out, int out_size)
{
    const float* in_seq = (const float*)d_in[0];
    const float* thK    = (const float*)d_in[1];
    const float* thV    = (const float*)d_in[2];
    const float* thQ    = (const float*)d_in[3];
    const float* W0     = (const float*)d_in[4];
    const float* b0     = (const float*)d_in[5];
    float* out = (float*)d_out;

    cudaFuncSetAttribute(scan_kernel, cudaFuncAttributeMaxDynamicSharedMemorySize, SCAN_SMEM);

    dim3 gproj((BB * SS) / GBM, DD / GBN, 3);   // 128 x 8 x 3
    proj_kernel<<<gproj, 256>>>(in_seq, thK, thV, thQ);

    dim3 gscan(DD / 64, BB);                    // 16 x 8 = 128 persistent blocks
    scan_kernel<<<gscan, 512, SCAN_SMEM>>>(W0, b0, out);
}

// round 13
// speedup vs baseline: 1.4411x; 1.4411x over previous
#include <cuda_runtime.h>

#define BB 8
#define SS 2048
#define DD 1024
#define LRATE 0.01f

typedef unsigned long long u64;

// Scratch for projected views K, V, Q: [B*S, D] each (64MB each).
__device__ float g_K[BB * SS * DD];
__device__ float g_V[BB * SS * DD];
__device__ float g_Q[BB * SS * DD];

// ---------------- packed f32x2 helpers (FFMA2: 2 MACs/instr) ----------------
__device__ __forceinline__ u64 pk2(float x, float y) {
    u64 r; asm("mov.b64 %0, {%1, %2};" : "=l"(r) : "f"(x), "f"(y)); return r;
}
__device__ __forceinline__ float2 upk2(u64 v) {
    float2 r; asm("mov.b64 {%0, %1}, %2;" : "=f"(r.x), "=f"(r.y) : "l"(v)); return r;
}
__device__ __forceinline__ u64 f2fma(u64 a, u64 b, u64 c) {
    u64 d; asm("fma.rn.f32x2 %0, %1, %2, %3;" : "=l"(d) : "l"(a), "l"(b), "l"(c)); return d;
}
__device__ __forceinline__ float warpsum(float v) {
#pragma unroll
    for (int o = 16; o > 0; o >>= 1) v += __shfl_xor_sync(0xffffffffu, v, o);
    return v;
}
__device__ __forceinline__ float redu(u64 v) {   // pair-sum + warp reduce
    const float2 p = upk2(v);
    return warpsum(p.x + p.y);
}

// ======================= Projection GEMM =======================
#define GBM 128
#define GBN 128
#define GBK 16
#define GPAD 132
#define KITERS (DD / GBK)     // 64

__global__ void __launch_bounds__(256, 1) proj_kernel(
    const float* __restrict__ A,
    const float* __restrict__ T0,
    const float* __restrict__ T1,
    const float* __restrict__ T2)
{
    __shared__ __align__(16) float As[GBK][GPAD];
    __shared__ __align__(16) float Bs[GBK][GPAD];

    const float* Th = (blockIdx.z == 0) ? T0 : ((blockIdx.z == 1) ? T1 : T2);
    float* C = (blockIdx.z == 0) ? g_K : ((blockIdx.z == 1) ? g_V : g_Q);

    const int m0 = blockIdx.x * GBM;
    const int n0 = blockIdx.y * GBN;
    const int tid = threadIdx.x;
    const int tx = tid & 15, ty = tid >> 4;

    u64 acc[8][4];
#pragma unroll
    for (int i = 0; i < 8; i++)
#pragma unroll
        for (int p = 0; p < 4; p++) acc[i][p] = 0ull;

    const int r0 = tid >> 2;
    const int kq = tid & 3;

    float4 ra0 = *(const float4*)&A [(m0 + r0)      * DD + 4 * kq];
    float4 ra1 = *(const float4*)&A [(m0 + r0 + 64) * DD + 4 * kq];
    float4 rb0 = *(const float4*)&Th[(n0 + r0)      * DD + 4 * kq];
    float4 rb1 = *(const float4*)&Th[(n0 + r0 + 64) * DD + 4 * kq];

    for (int kt = 0; kt < KITERS; kt++) {
        As[4 * kq + 0][r0] = ra0.x; As[4 * kq + 1][r0] = ra0.y;
        As[4 * kq + 2][r0] = ra0.z; As[4 * kq + 3][r0] = ra0.w;
        As[4 * kq + 0][r0 + 64] = ra1.x; As[4 * kq + 1][r0 + 64] = ra1.y;
        As[4 * kq + 2][r0 + 64] = ra1.z; As[4 * kq + 3][r0 + 64] = ra1.w;
        Bs[4 * kq + 0][r0] = rb0.x; Bs[4 * kq + 1][r0] = rb0.y;
        Bs[4 * kq + 2][r0] = rb0.z; Bs[4 * kq + 3][r0] = rb0.w;
        Bs[4 * kq + 0][r0 + 64] = rb1.x; Bs[4 * kq + 1][r0 + 64] = rb1.y;
        Bs[4 * kq + 2][r0 + 64] = rb1.z; Bs[4 * kq + 3][r0 + 64] = rb1.w;
        __syncthreads();

        if (kt + 1 < KITERS) {
            const int kb = (kt + 1) * GBK + 4 * kq;
            ra0 = *(const float4*)&A [(m0 + r0)      * DD + kb];
            ra1 = *(const float4*)&A [(m0 + r0 + 64) * DD + kb];
            rb0 = *(const float4*)&Th[(n0 + r0)      * DD + kb];
            rb1 = *(const float4*)&Th[(n0 + r0 + 64) * DD + kb];
        }

#pragma unroll
        for (int kk = 0; kk < GBK; kk++) {
            const float4 a0 = *(const float4*)&As[kk][ty * 8];
            const float4 a1 = *(const float4*)&As[kk][ty * 8 + 4];
            const ulonglong2 b01 = *(const ulonglong2*)&Bs[kk][tx * 8];
            const ulonglong2 b23 = *(const ulonglong2*)&Bs[kk][tx * 8 + 4];
            u64 bp[4] = {b01.x, b01.y, b23.x, b23.y};
            const float av[8] = {a0.x, a0.y, a0.z, a0.w, a1.x, a1.y, a1.z, a1.w};
#pragma unroll
            for (int i = 0; i < 8; i++) {
                const u64 ap = pk2(av[i], av[i]);
#pragma unroll
                for (int p = 0; p < 4; p++) acc[i][p] = f2fma(ap, bp[p], acc[i][p]);
            }
        }
        __syncthreads();
    }

#pragma unroll
    for (int i = 0; i < 8; i++) {
        const int m = m0 + ty * 8 + i;
        const float2 q0 = upk2(acc[i][0]), q1 = upk2(acc[i][1]);
        const float2 q2 = upk2(acc[i][2]), q3 = upk2(acc[i][3]);
        *(float4*)&C[m * DD + n0 + tx * 8]     = make_float4(q0.x, q0.y, q1.x, q1.y);
        *(float4*)&C[m * DD + n0 + tx * 8 + 4] = make_float4(q2.x, q2.y, q3.x, q3.y);
    }
}

// ======================= Persistent TTT scan v2 =======================
// 128 blocks (16 row-chunks x 8 batches), 256 threads (8 warps).
// Warp w owns 8 rows: rows 0..5 in SMEM (48 rows/block = 192KB), rows 6,7 in
// registers. Rows processed as two independent quads (4 rows each):
//   A (dk = W0.k) -> recurrence -> B (rank-4 update fused with dq = W4.q).
// KK/KQ cross-dot scalars computed cooperatively once per block per group.
#define SMEM_ROWS 48
#define SCAN_SMEM (SMEM_ROWS * DD * 4)
#define TSTRIDE (DD / 4)      // ulonglong2 (16B) per token row = 256

__global__ void __launch_bounds__(256, 1) scan_kernel(
    const float* __restrict__ W0,
    const float* __restrict__ b0,
    float* __restrict__ out)
{
    extern __shared__ __align__(16) float Wsh[];
    __shared__ float xred[2][12][8];          // double-buffered cross-dot partials
    ulonglong2* Wsh2 = (ulonglong2*)Wsh;

    const int tid = threadIdx.x;
    const int w = tid >> 5;
    const int lane = tid & 31;
    const int batch = blockIdx.y;
    const int row0 = blockIdx.x * 64;
    const int rbase = row0 + 8 * w;           // first of this warp's 8 rows

    // ---- init W slice: smem slot s (0..47) -> global row row0 + (s/6)*8 + s%6
    {
        const float4* W04 = (const float4*)W0;
        float4* Wsh4 = (float4*)Wsh;
        for (int i = tid; i < SMEM_ROWS * 256; i += 256) {
            const int s = i >> 8;
            const int c = i & 255;
            const int grow = row0 + (s / 6) * 8 + (s % 6);
            Wsh4[i] = W04[grow * 256 + c];
        }
    }
    ulonglong2 wr6[8], wr7[8];                // register rows rbase+6, rbase+7
    {
        const ulonglong2* W02 = (const ulonglong2*)W0;
#pragma unroll
        for (int j = 0; j < 8; j++) {
            wr6[j] = W02[(rbase + 6) * 256 + lane + 32 * j];
            wr7[j] = W02[(rbase + 7) * 256 + lane + 32 * j];
        }
    }
    float bv[8];
#pragma unroll
    for (int i = 0; i < 8; i++) bv[i] = b0[rbase + i];
    __syncthreads();

    const ulonglong2* kB = (const ulonglong2*)(g_K + batch * SS * DD);
    const ulonglong2* qB = (const ulonglong2*)(g_Q + batch * SS * DD);
    const float* Vb = g_V + batch * SS * DD;
    float* Ob = out + (size_t)batch * SS * DD;

    const float cm = -LRATE * 2.0f / (float)DD;
    const int s0 = (6 * w + 0) * 256 + lane;
    const int s1 = (6 * w + 1) * 256 + lane;
    const int s2 = (6 * w + 2) * 256 + lane;
    const int s3 = (6 * w + 3) * 256 + lane;
    const int s4 = (6 * w + 4) * 256 + lane;
    const int s5 = (6 * w + 5) * 256 + lane;

    for (int gt = 0; gt < SS / 4; gt++) {
        const int buf = gt & 1;

        // ===== phase 0: cooperative cross dots (each warp: 1/8 of dims) =====
        {
            const int i0 = (w << 5) + lane;   // one ulonglong2 (4 floats) per lane
            const ulonglong2 K0 = __ldg(kB + i0);
            const ulonglong2 K1 = __ldg(kB + i0 + TSTRIDE);
            const ulonglong2 K2 = __ldg(kB + i0 + 2 * TSTRIDE);
            const ulonglong2 K3 = __ldg(kB + i0 + 3 * TSTRIDE);
            const ulonglong2 Q0 = __ldg(qB + i0);
            const ulonglong2 Q1 = __ldg(qB + i0 + TSTRIDE);
            const ulonglong2 Q2 = __ldg(qB + i0 + 2 * TSTRIDE);
            u64 cr[12];
            // KK: 01 02 03 12 13 23
            cr[0] = f2fma(K0.y, K1.y, f2fma(K0.x, K1.x, 0ull));
            cr[1] = f2fma(K0.y, K2.y, f2fma(K0.x, K2.x, 0ull));
            cr[2] = f2fma(K0.y, K3.y, f2fma(K0.x, K3.x, 0ull));
            cr[3] = f2fma(K1.y, K2.y, f2fma(K1.x, K2.x, 0ull));
            cr[4] = f2fma(K1.y, K3.y, f2fma(K1.x, K3.x, 0ull));
            cr[5] = f2fma(K2.y, K3.y, f2fma(K2.x, K3.x, 0ull));
            // KQ: k1.q0 k2.q0 k3.q0 k2.q1 k3.q1 k3.q2
            cr[6]  = f2fma(K1.y, Q0.y, f2fma(K1.x, Q0.x, 0ull));
            cr[7]  = f2fma(K2.y, Q0.y, f2fma(K2.x, Q0.x, 0ull));
            cr[8]  = f2fma(K3.y, Q0.y, f2fma(K3.x, Q0.x, 0ull));
            cr[9]  = f2fma(K2.y, Q1.y, f2fma(K2.x, Q1.x, 0ull));
            cr[10] = f2fma(K3.y, Q1.y, f2fma(K3.x, Q1.x, 0ull));
            cr[11] = f2fma(K3.y, Q2.y, f2fma(K3.x, Q2.x, 0ull));
#pragma unroll
            for (int p = 0; p < 12; p++) {
                const float pv = redu(cr[p]);
                if (lane == 0) xred[buf][p][w] = pv;
            }
        }
        __syncthreads();
        float KKp[6], KQp[6];
#pragma unroll
        for (int p = 0; p < 6; p++) {
            float sk = 1.0f, sq = 1.0f;
#pragma unroll
            for (int ww = 0; ww < 8; ww++) { sk += xred[buf][p][ww]; sq += xred[buf][p + 6][ww]; }
            KKp[p] = sk; KQp[p] = sq;
        }

        // =================== QUAD 0: rows rbase+0..3 (smem) =================
        {
            u64 dka[16];
#pragma unroll
            for (int i = 0; i < 16; i++) dka[i] = 0ull;
#pragma unroll
            for (int j = 0; j < 8; j++) {
                const int idx = lane + 32 * j;
                const ulonglong2 a = Wsh2[s0 + 32 * j];
                const ulonglong2 b = Wsh2[s1 + 32 * j];
                const ulonglong2 c = Wsh2[s2 + 32 * j];
                const ulonglong2 d = Wsh2[s3 + 32 * j];
#pragma unroll
                for (int t = 0; t < 4; t++) {
                    const ulonglong2 kv = __ldg(kB + idx + t * TSTRIDE);
                    dka[t*4+0] = f2fma(a.y, kv.y, f2fma(a.x, kv.x, dka[t*4+0]));
                    dka[t*4+1] = f2fma(b.y, kv.y, f2fma(b.x, kv.x, dka[t*4+1]));
                    dka[t*4+2] = f2fma(c.y, kv.y, f2fma(c.x, kv.x, dka[t*4+2]));
                    dka[t*4+3] = f2fma(d.y, kv.y, f2fma(d.x, kv.x, dka[t*4+3]));
                }
            }
            float dkb[16];
#pragma unroll
            for (int i = 0; i < 16; i++) dkb[i] = redu(dka[i]);

            const float4 v0 = __ldg((const float4*)(Vb + 0 * DD + rbase));
            const float4 v1 = __ldg((const float4*)(Vb + 1 * DD + rbase));
            const float4 v2 = __ldg((const float4*)(Vb + 2 * DD + rbase));
            const float4 v3 = __ldg((const float4*)(Vb + 3 * DD + rbase));
            const float vv[16] = {v0.x,v0.y,v0.z,v0.w, v1.x,v1.y,v1.z,v1.w,
                                  v2.x,v2.y,v2.z,v2.w, v3.x,v3.y,v3.z,v3.w};
            u64 mgp[16];
#pragma unroll
            for (int r = 0; r < 4; r++) {
                const float m0v = cm * (dkb[0+r]  + bv[r] - vv[0+r]);
                const float m1v = cm * (dkb[4+r]  + bv[r] + m0v*KKp[0] - vv[4+r]);
                const float m2v = cm * (dkb[8+r]  + bv[r] + m0v*KKp[1] + m1v*KKp[3] - vv[8+r]);
                const float m3v = cm * (dkb[12+r] + bv[r] + m0v*KKp[2] + m1v*KKp[4] + m2v*KKp[5] - vv[12+r]);
                mgp[0+r] = pk2(m0v, m0v); mgp[4+r] = pk2(m1v, m1v);
                mgp[8+r] = pk2(m2v, m2v); mgp[12+r] = pk2(m3v, m3v);
                bv[r] += m0v + m1v + m2v + m3v;
            }

            u64 dqa[16];
#pragma unroll
            for (int i = 0; i < 16; i++) dqa[i] = 0ull;
#pragma unroll
            for (int j = 0; j < 8; j++) {
                const int idx = lane + 32 * j;
                ulonglong2 a = Wsh2[s0 + 32 * j];
                ulonglong2 b = Wsh2[s1 + 32 * j];
                ulonglong2 c = Wsh2[s2 + 32 * j];
                ulonglong2 d = Wsh2[s3 + 32 * j];
#pragma unroll
                for (int t = 0; t < 4; t++) {
                    const ulonglong2 kv = __ldg(kB + idx + t * TSTRIDE);
                    a.x = f2fma(mgp[t*4+0], kv.x, a.x); a.y = f2fma(mgp[t*4+0], kv.y, a.y);
                    b.x = f2fma(mgp[t*4+1], kv.x, b.x); b.y = f2fma(mgp[t*4+1], kv.y, b.y);
                    c.x = f2fma(mgp[t*4+2], kv.x, c.x); c.y = f2fma(mgp[t*4+2], kv.y, c.y);
                    d.x = f2fma(mgp[t*4+3], kv.x, d.x); d.y = f2fma(mgp[t*4+3], kv.y, d.y);
                }
                Wsh2[s0 + 32 * j] = a;
                Wsh2[s1 + 32 * j] = b;
                Wsh2[s2 + 32 * j] = c;
                Wsh2[s3 + 32 * j] = d;
#pragma unroll
                for (int t = 0; t < 4; t++) {
                    const ulonglong2 qv = __ldg(qB + idx + t * TSTRIDE);
                    dqa[t*4+0] = f2fma(a.y, qv.y, f2fma(a.x, qv.x, dqa[t*4+0]));
                    dqa[t*4+1] = f2fma(b.y, qv.y, f2fma(b.x, qv.x, dqa[t*4+1]));
                    dqa[t*4+2] = f2fma(c.y, qv.y, f2fma(c.x, qv.x, dqa[t*4+2]));
                    dqa[t*4+3] = f2fma(d.y, qv.y, f2fma(d.x, qv.x, dqa[t*4+3]));
                }
            }
            float dqs[16];
#pragma unroll
            for (int i = 0; i < 16; i++) dqs[i] = redu(dqa[i]);

            if (lane == 0) {
                float o[16];
#pragma unroll
                for (int r = 0; r < 4; r++) {
                    const float m1f = upk2(mgp[4+r]).x;
                    const float m2f = upk2(mgp[8+r]).x;
                    const float m3f = upk2(mgp[12+r]).x;
                    o[0+r]  = dqs[0+r]  + bv[r] - (m1f*KQp[0] + m2f*KQp[1] + m3f*KQp[2]);
                    o[4+r]  = dqs[4+r]  + bv[r] - (m2f*KQp[3] + m3f*KQp[4]);
                    o[8+r]  = dqs[8+r]  + bv[r] - (m3f*KQp[5]);
                    o[12+r] = dqs[12+r] + bv[r];
                }
                *(float4*)(Ob + 0 * DD + rbase) = make_float4(o[0],  o[1],  o[2],  o[3]);
                *(float4*)(Ob + 1 * DD + rbase) = make_float4(o[4],  o[5],  o[6],  o[7]);
                *(float4*)(Ob + 2 * DD + rbase) = make_float4(o[8],  o[9],  o[10], o[11]);
                *(float4*)(Ob + 3 * DD + rbase) = make_float4(o[12], o[13], o[14], o[15]);
            }
        }

        // ============ QUAD 1: rows rbase+4..7 (2 smem + 2 register) =========
        {
            u64 dka[16];
#pragma unroll
            for (int i = 0; i < 16; i++) dka[i] = 0ull;
#pragma unroll
            for (int j = 0; j < 8; j++) {
                const int idx = lane + 32 * j;
                const ulonglong2 a = Wsh2[s4 + 32 * j];
                const ulonglong2 b = Wsh2[s5 + 32 * j];
                const ulonglong2 c = wr6[j];
                const ulonglong2 d = wr7[j];
#pragma unroll
                for (int t = 0; t < 4; t++) {
                    const ulonglong2 kv = __ldg(kB + idx + t * TSTRIDE);
                    dka[t*4+0] = f2fma(a.y, kv.y, f2fma(a.x, kv.x, dka[t*4+0]));
                    dka[t*4+1] = f2fma(b.y, kv.y, f2fma(b.x, kv.x, dka[t*4+1]));
                    dka[t*4+2] = f2fma(c.y, kv.y, f2fma(c.x, kv.x, dka[t*4+2]));
                    dka[t*4+3] = f2fma(d.y, kv.y, f2fma(d.x, kv.x, dka[t*4+3]));
                }
            }
            float dkb[16];
#pragma unroll
            for (int i = 0; i < 16; i++) dkb[i] = redu(dka[i]);

            const float4 v0 = __ldg((const float4*)(Vb + 0 * DD + rbase + 4));
            const float4 v1 = __ldg((const float4*)(Vb + 1 * DD + rbase + 4));
            const float4 v2 = __ldg((const float4*)(Vb + 2 * DD + rbase + 4));
            const float4 v3 = __ldg((const float4*)(Vb + 3 * DD + rbase + 4));
            const float vv[16] = {v0.x,v0.y,v0.z,v0.w, v1.x,v1.y,v1.z,v1.w,
                                  v2.x,v2.y,v2.z,v2.w, v3.x,v3.y,v3.z,v3.w};
            u64 mgp[16];
#pragma unroll
            for (int r = 0; r < 4; r++) {
                const float m0v = cm * (dkb[0+r]  + bv[4+r] - vv[0+r]);
                const float m1v = cm * (dkb[4+r]  + bv[4+r] + m0v*KKp[0] - vv[4+r]);
                const float m2v = cm * (dkb[8+r]  + bv[4+r] + m0v*KKp[1] + m1v*KKp[3] - vv[8+r]);
                const float m3v = cm * (dkb[12+r] + bv[4+r] + m0v*KKp[2] + m1v*KKp[4] + m2v*KKp[5] - vv[12+r]);
                mgp[0+r] = pk2(m0v, m0v); mgp[4+r] = pk2(m1v, m1v);
                mgp[8+r] = pk2(m2v, m2v); mgp[12+r] = pk2(m3v, m3v);
                bv[4+r] += m0v + m1v + m2v + m3v;
            }

            u64 dqa[16];
#pragma unroll
            for (int i = 0; i < 16; i++) dqa[i] = 0ull;
#pragma unroll
            for (int j = 0; j < 8; j++) {
                const int idx = lane + 32 * j;
                ulonglong2 a = Wsh2[s4 + 32 * j];
                ulonglong2 b = Wsh2[s5 + 32 * j];
                ulonglong2 c = wr6[j];
                ulonglong2 d = wr7[j];
#pragma unroll
                for (int t = 0; t < 4; t++) {
                    const ulonglong2 kv = __ldg(kB + idx + t * TSTRIDE);
                    a.x = f2fma(mgp[t*4+0], kv.x, a.x); a.y = f2fma(mgp[t*4+0], kv.y, a.y);
                    b.x = f2fma(mgp[t*4+1], kv.x, b.x); b.y = f2fma(mgp[t*4+1], kv.y, b.y);
                    c.x = f2fma(mgp[t*4+2], kv.x, c.x); c.y = f2fma(mgp[t*4+2], kv.y, c.y);
                    d.x = f2fma(mgp[t*4+3], kv.x, d.x); d.y = f2fma(mgp[t*4+3], kv.y, d.y);
                }
                Wsh2[s4 + 32 * j] = a;
                Wsh2[s5 + 32 * j] = b;
                wr6[j] = c;
                wr7[j] = d;
#pragma unroll
                for (int t = 0; t < 4; t++) {
                    const ulonglong2 qv = __ldg(qB + idx + t * TSTRIDE);
                    dqa[t*4+0] = f2fma(a.y, qv.y, f2fma(a.x, qv.x, dqa[t*4+0]));
                    dqa[t*4+1] = f2fma(b.y, qv.y, f2fma(b.x, qv.x, dqa[t*4+1]));
                    dqa[t*4+2] = f2fma(c.y, qv.y, f2fma(c.x, qv.x, dqa[t*4+2]));
                    dqa[t*4+3] = f2fma(d.y, qv.y, f2fma(d.x, qv.x, dqa[t*4+3]));
                }
            }
            float dqs[16];
#pragma unroll
            for (int i = 0; i < 16; i++) dqs[i] = redu(dqa[i]);

            if (lane == 0) {
                float o[16];
#pragma unroll
                for (int r = 0; r < 4; r++) {
                    const float m1f = upk2(mgp[4+r]).x;
                    const float m2f = upk2(mgp[8+r]).x;
                    const float m3f = upk2(mgp[12+r]).x;
                    o[0+r]  = dqs[0+r]  + bv[4+r] - (m1f*KQp[0] + m2f*KQp[1] + m3f*KQp[2]);
                    o[4+r]  = dqs[4+r]  + bv[4+r] - (m2f*KQp[3] + m3f*KQp[4]);
                    o[8+r]  = dqs[8+r]  + bv[4+r] - (m3f*KQp[5]);
                    o[12+r] = dqs[12+r] + bv[4+r];
                }
                *(float4*)(Ob + 0 * DD + rbase + 4) = make_float4(o[0],  o[1],  o[2],  o[3]);
                *(float4*)(Ob + 1 * DD + rbase + 4) = make_float4(o[4],  o[5],  o[6],  o[7]);
                *(float4*)(Ob + 2 * DD + rbase + 4) = make_float4(o[8],  o[9],  o[10], o[11]);
                *(float4*)(Ob + 3 * DD + rbase + 4) = make_float4(o[12], o[13], o[14], o[15]);
            }
        }

        // advance to next 4-token group
        kB += 4 * TSTRIDE;
        qB += 4 * TSTRIDE;
        Vb += 4 * DD;
        Ob += 4 * DD;
    }
}

// ======================= launch =======================
extern "C" void kernel_launch(void* const* d_in, const int* in_sizes, int n_in,
                              void* d_out, int out_size)
{
    const float* in_seq = (const float*)d_in[0];
    const float* thK    = (const float*)d_in[1];
    const float* thV    = (const float*)d_in[2];
    const float* thQ    = (const float*)d_in[3];
    const float* W0     = (const float*)d_in[4];
    const float* b0     = (const float*)d_in[5];
    float* out = (float*)d_out;

    cudaFuncSetAttribute(scan_kernel, cudaFuncAttributeMaxDynamicSharedMemorySize, SCAN_SMEM);

    dim3 gproj((BB * SS) / GBM, DD / GBN, 3);   // 128 x 8 x 3
    proj_kernel<<<gproj, 256>>>(in_seq, thK, thV, thQ);

    dim3 gscan(DD / 64, BB);                    // 16 x 8 = 128 persistent blocks
    scan_kernel<<<gscan, 256, SCAN_SMEM>>>(W0, b0, out);
}